// round 6
// baseline (speedup 1.0000x reference)
#include <cuda_runtime.h>
#include <cuda_fp16.h>
#include <cstdint>

// Problem constants
constexpr int BB = 256;    // batch
constexpr int KK = 8;      // in_size
constexpr int II = 1152;   // in_node_num
constexpr int NN = 10;     // num_node
constexpr int OO = 16;     // node_size
constexpr int IK = II * KK;   // 9216
constexpr int NO = NN * OO;   // 160
constexpr int KC = 36;        // split-K chunks for s-GEMM
constexpr int KCW = IK / KC;  // 256
constexpr int NBLK = 144;     // persistent grid (<=148 SMs, single wave)

// Static device scratch (~24 MB total, L2-resident)
__device__ __half g_xh [BB * IK];     // xh[b][i*8+k]
__device__ __half g_xhT[IK * BB];     // xhT[i*8+k][b]
__device__ float  g_Wps[II * NO * KK];// 0.03*W, [i][n][o][k]
__device__ __half g_A  [NO * IK];     // A[no][ik] = c[i,n]*Wps
__device__ float  g_sp [KC][BB * NO]; // split-K partials
__device__ __half g_vT [NO * BB];     // vT[no][b]
__device__ float  g_bij[II * NN];

// grid barrier state (replay-safe: count self-resets, gen is monotonic)
__device__ unsigned g_count = 0;
__device__ unsigned g_gen   = 0;

__device__ __forceinline__ unsigned ld_acq(const unsigned* p) {
    unsigned v;
    asm volatile("ld.acquire.gpu.global.u32 %0, [%1];" : "=r"(v) : "l"(p));
    return v;
}

__device__ __forceinline__ void gridbar() {
    __syncthreads();
    if (threadIdx.x == 0) {
        __threadfence();
        unsigned mygen = ld_acq(&g_gen);
        unsigned prev = atomicAdd(&g_count, 1);
        if (prev == NBLK - 1) {
            g_count = 0;            // sole writer at this point
            __threadfence();
            atomicAdd(&g_gen, 1);
        } else {
            while (ld_acq(&g_gen) == mygen) __nanosleep(32);
        }
    }
    __syncthreads();
}

// shared memory union across phases
struct SmemU {
    union {
        float tf[32][32][9];                               // prep_x staging
        struct { __half A[64][72]; __half B[160][72]; } gm; // GEMM tiles
    } u;
    float suv[8][10];
    float cs[8][10];
};

// ---------------------------------------------------------------------------
__device__ __forceinline__ void mma16816(float* c, uint32_t a0, uint32_t a1,
                                         uint32_t a2, uint32_t a3,
                                         uint32_t b0, uint32_t b1) {
    asm volatile(
        "mma.sync.aligned.m16n8k16.row.col.f32.f16.f16.f32 "
        "{%0,%1,%2,%3}, {%4,%5,%6,%7}, {%8,%9}, {%0,%1,%2,%3};"
        : "+f"(c[0]), "+f"(c[1]), "+f"(c[2]), "+f"(c[3])
        : "r"(a0), "r"(a1), "r"(a2), "r"(a3), "r"(b0), "r"(b1));
}

__device__ __forceinline__ uint32_t ld_h2(const __half* p) {
    return *reinterpret_cast<const uint32_t*>(p);
}

// ---------------------------------------------------------------------------
// Phase: pack x -> xh (b-major) and xhT (ik-major), fp16
__device__ void prep_x_phase(SmemU& sm, const float* __restrict__ x) {
    int t = threadIdx.x;
    for (int tile = blockIdx.x; tile < 288; tile += NBLK) {
        int i0 = (tile % 36) * 32, b0 = (tile / 36) * 32;
        int kk = t >> 5, il = t & 31;
#pragma unroll
        for (int j = 0; j < 32; j++)
            sm.u.tf[j][il][kk] = x[((size_t)(b0 + j) * KK + kk) * II + i0 + il];
        __syncthreads();
#pragma unroll
        for (int jj = 0; jj < 4; jj++) {
            int s = jj * 256 + t;
            int bl = s >> 5, u = s & 31;
            __half h[8];
#pragma unroll
            for (int k = 0; k < 8; k++) h[k] = __float2half_rn(sm.u.tf[bl][u][k]);
            *reinterpret_cast<uint4*>(&g_xh[(size_t)(b0 + bl) * IK + (i0 + u) * 8]) =
                *reinterpret_cast<const uint4*>(h);
        }
#pragma unroll
        for (int jj = 0; jj < 4; jj++) {
            int s = jj * 256 + t;
            int row = s >> 2, w = s & 3;
            int il2 = row >> 3, k = row & 7;
            __half h[8];
#pragma unroll
            for (int bb = 0; bb < 8; bb++) h[bb] = __float2half_rn(sm.u.tf[w * 8 + bb][il2][k]);
            *reinterpret_cast<uint4*>(&g_xhT[(size_t)((i0 + il2) * 8 + k) * BB + b0 + w * 8]) =
                *reinterpret_cast<const uint4*>(h);
        }
        __syncthreads();
    }
}

// Phase: Wps = 0.03*W ; A0 = 0.1*Wps  (exactly 5 strided rounds)
__device__ void prep_w_phase(const float* __restrict__ W) {
    for (int tid = blockIdx.x * 256 + threadIdx.x; tid < II * NO; tid += NBLK * 256) {
        float4 w0 = *reinterpret_cast<const float4*>(&W[(size_t)tid * 8]);
        float4 w1 = *reinterpret_cast<const float4*>(&W[(size_t)tid * 8 + 4]);
        const float s = 0.03f;
        float4 p0 = make_float4(s * w0.x, s * w0.y, s * w0.z, s * w0.w);
        float4 p1 = make_float4(s * w1.x, s * w1.y, s * w1.z, s * w1.w);
        *reinterpret_cast<float4*>(&g_Wps[(size_t)tid * 8]) = p0;
        *reinterpret_cast<float4*>(&g_Wps[(size_t)tid * 8 + 4]) = p1;
        int i = tid / NO, no = tid % NO;
        __half h[8];
        h[0] = __float2half_rn(0.1f * p0.x); h[1] = __float2half_rn(0.1f * p0.y);
        h[2] = __float2half_rn(0.1f * p0.z); h[3] = __float2half_rn(0.1f * p0.w);
        h[4] = __float2half_rn(0.1f * p1.x); h[5] = __float2half_rn(0.1f * p1.y);
        h[6] = __float2half_rn(0.1f * p1.z); h[7] = __float2half_rn(0.1f * p1.w);
        *reinterpret_cast<uint4*>(&g_A[(size_t)no * IK + i * 8]) =
            *reinterpret_cast<const uint4*>(h);
    }
}

// Phase: split-K s-GEMM  sp[kc][b][no] = sum_{ik in chunk} xh[b][ik]*A[no][ik]
__device__ void sgemm_phase(SmemU& sm) {
    int t = threadIdx.x;
    int bm = blockIdx.x & 3, kc = blockIdx.x >> 2;
    int b0 = bm * 64, kbase = kc * KCW;
    int warp = t >> 5, lane = t & 31;
    int wm = warp >> 1, wn = warp & 1;
    int gr = lane >> 2, tc = lane & 3;

    float acc[10][4];
#pragma unroll
    for (int f = 0; f < 10; f++)
#pragma unroll
        for (int q = 0; q < 4; q++) acc[f][q] = 0.0f;

    for (int st = 0; st < 4; st++) {
        int ks = kbase + st * 64;
#pragma unroll
        for (int j = 0; j < 2; j++) {
            int s = j * 256 + t, r = s >> 3, u = s & 7;
            *reinterpret_cast<uint4*>(&sm.u.gm.A[r][u * 8]) =
                *reinterpret_cast<const uint4*>(&g_xh[(size_t)(b0 + r) * IK + ks + u * 8]);
        }
#pragma unroll
        for (int j = 0; j < 5; j++) {
            int s = j * 256 + t, r = s >> 3, u = s & 7;
            *reinterpret_cast<uint4*>(&sm.u.gm.B[r][u * 8]) =
                *reinterpret_cast<const uint4*>(&g_A[(size_t)r * IK + ks + u * 8]);
        }
        __syncthreads();
#pragma unroll
        for (int kk = 0; kk < 4; kk++) {
            int col = kk * 16;
            uint32_t a0 = ld_h2(&sm.u.gm.A[wm * 16 + gr][col + 2 * tc]);
            uint32_t a1 = ld_h2(&sm.u.gm.A[wm * 16 + gr + 8][col + 2 * tc]);
            uint32_t a2 = ld_h2(&sm.u.gm.A[wm * 16 + gr][col + 2 * tc + 8]);
            uint32_t a3 = ld_h2(&sm.u.gm.A[wm * 16 + gr + 8][col + 2 * tc + 8]);
#pragma unroll
            for (int f = 0; f < 10; f++) {
                int br = wn * 80 + f * 8 + gr;
                uint32_t bb0 = ld_h2(&sm.u.gm.B[br][col + 2 * tc]);
                uint32_t bb1 = ld_h2(&sm.u.gm.B[br][col + 2 * tc + 8]);
                mma16816(acc[f], a0, a1, a2, a3, bb0, bb1);
            }
        }
        __syncthreads();
    }
#pragma unroll
    for (int f = 0; f < 10; f++) {
        int no = wn * 80 + f * 8 + 2 * tc;
        int r0 = b0 + wm * 16 + gr;
        *reinterpret_cast<float2*>(&g_sp[kc][(size_t)r0 * NO + no]) =
            make_float2(acc[f][0], acc[f][1]);
        *reinterpret_cast<float2*>(&g_sp[kc][(size_t)(r0 + 8) * NO + no]) =
            make_float2(acc[f][2], acc[f][3]);
    }
}

// Phase: reduce split-K + squash. slot = b*160+no; 16-lane groups aligned.
__device__ void squash_phase(float* __restrict__ out, int last) {
    for (int slot = blockIdx.x * 256 + threadIdx.x; slot < BB * NO; slot += NBLK * 256) {
        float s = 0.0f;
#pragma unroll
        for (int kc = 0; kc < KC; kc++) s += g_sp[kc][slot];
        float m = s * s;
        m += __shfl_xor_sync(0xffffffffu, m, 1);
        m += __shfl_xor_sync(0xffffffffu, m, 2);
        m += __shfl_xor_sync(0xffffffffu, m, 4);
        m += __shfl_xor_sync(0xffffffffu, m, 8);
        float v = s * (sqrtf(m) / (1.0f + m));
        if (last) {
            out[slot] = v;
        } else {
            int b = slot / NO, no = slot % NO;
            g_vT[(size_t)no * BB + b] = __float2half_rn(v);
        }
    }
}

// Phase: uv-GEMM + routing update + A-build (block owns 8 i's = 64 ik rows)
__device__ void uv_phase(SmemU& sm, int first) {
    int t = threadIdx.x;
    int iblk0 = blockIdx.x * 8;
    int ikbase = blockIdx.x * 64;
    int warp = t >> 5, lane = t & 31;
    int wm = warp >> 1, wn = warp & 1;
    int gr = lane >> 2, tc = lane & 3;

    float acc[10][4];
#pragma unroll
    for (int f = 0; f < 10; f++)
#pragma unroll
        for (int q = 0; q < 4; q++) acc[f][q] = 0.0f;

    for (int st = 0; st < 4; st++) {
        int bs = st * 64;
#pragma unroll
        for (int j = 0; j < 2; j++) {
            int s = j * 256 + t, r = s >> 3, u = s & 7;
            *reinterpret_cast<uint4*>(&sm.u.gm.A[r][u * 8]) =
                *reinterpret_cast<const uint4*>(&g_xhT[(size_t)(ikbase + r) * BB + bs + u * 8]);
        }
#pragma unroll
        for (int j = 0; j < 5; j++) {
            int s = j * 256 + t, r = s >> 3, u = s & 7;
            *reinterpret_cast<uint4*>(&sm.u.gm.B[r][u * 8]) =
                *reinterpret_cast<const uint4*>(&g_vT[(size_t)r * BB + bs + u * 8]);
        }
        __syncthreads();
#pragma unroll
        for (int kk = 0; kk < 4; kk++) {
            int col = kk * 16;
            uint32_t a0 = ld_h2(&sm.u.gm.A[wm * 16 + gr][col + 2 * tc]);
            uint32_t a1 = ld_h2(&sm.u.gm.A[wm * 16 + gr + 8][col + 2 * tc]);
            uint32_t a2 = ld_h2(&sm.u.gm.A[wm * 16 + gr][col + 2 * tc + 8]);
            uint32_t a3 = ld_h2(&sm.u.gm.A[wm * 16 + gr + 8][col + 2 * tc + 8]);
#pragma unroll
            for (int f = 0; f < 10; f++) {
                int br = wn * 80 + f * 8 + gr;
                uint32_t bb0 = ld_h2(&sm.u.gm.B[br][col + 2 * tc]);
                uint32_t bb1 = ld_h2(&sm.u.gm.B[br][col + 2 * tc + 8]);
                mma16816(acc[f], a0, a1, a2, a3, bb0, bb1);
            }
        }
        __syncthreads();
    }

    // epilogue: weight C frags with Wps, reduce over (k,o)
    int i0g = iblk0 + wm * 2;
    int i1g = i0g + 1;
    float p[2][5];
#pragma unroll
    for (int il = 0; il < 2; il++)
#pragma unroll
        for (int nl = 0; nl < 5; nl++) p[il][nl] = 0.0f;

#pragma unroll
    for (int f = 0; f < 10; f++) {
        int no = wn * 80 + f * 8 + 2 * tc;
        int n = no >> 4, o = no & 15;
        float w00 = g_Wps[(((size_t)i0g * NN + n) * OO + o) * KK + gr];
        float w01 = g_Wps[(((size_t)i0g * NN + n) * OO + o + 1) * KK + gr];
        float w10 = g_Wps[(((size_t)i1g * NN + n) * OO + o) * KK + gr];
        float w11 = g_Wps[(((size_t)i1g * NN + n) * OO + o + 1) * KK + gr];
        int nl = f >> 1;
        p[0][nl] += acc[f][0] * w00 + acc[f][1] * w01;
        p[1][nl] += acc[f][2] * w10 + acc[f][3] * w11;
    }
#pragma unroll
    for (int il = 0; il < 2; il++)
#pragma unroll
        for (int nl = 0; nl < 5; nl++) {
            float v = p[il][nl];
#pragma unroll
            for (int off = 16; off > 0; off >>= 1)
                v += __shfl_xor_sync(0xffffffffu, v, off);
            if (lane == 0) sm.suv[wm * 2 + il][wn * 5 + nl] = v;
        }
    __syncthreads();

    if (t < 8) {
        int i = iblk0 + t;
        float bv[NN];
        float mx = -1e30f;
#pragma unroll
        for (int n = 0; n < NN; n++) {
            float bp = first ? 0.0f : g_bij[i * NN + n];
            bv[n] = bp + sm.suv[t][n] * (1.0f / BB);
            g_bij[i * NN + n] = bv[n];
            mx = fmaxf(mx, bv[n]);
        }
        float sum = 0.0f;
#pragma unroll
        for (int n = 0; n < NN; n++) { bv[n] = __expf(bv[n] - mx); sum += bv[n]; }
        float inv = 1.0f / sum;
#pragma unroll
        for (int n = 0; n < NN; n++) sm.cs[t][n] = bv[n] * inv;
    }
    __syncthreads();

    // A-build for this block's 64 ik rows: A[no][ik] = c[i,n]*Wps
#pragma unroll
    for (int j = 0; j < 20; j++) {
        int s = j * 256 + t;
        int no = s >> 5, cp = s & 31;
        int k2 = cp * 2;
        int il = cp >> 2, k = k2 & 7;
        int n = no >> 4, o = no & 15;
        float2 wv = *reinterpret_cast<const float2*>(
            &g_Wps[(((size_t)(iblk0 + il) * NN + n) * OO + o) * KK + k]);
        float cc = sm.cs[il][n];
        __half2 h = __floats2half2_rn(cc * wv.x, cc * wv.y);
        *reinterpret_cast<__half2*>(&g_A[(size_t)no * IK + ikbase + k2]) = h;
    }
    __syncthreads();
}

// ---------------------------------------------------------------------------
__global__ __launch_bounds__(256) void k_mega(const float* __restrict__ x,
                                              const float* __restrict__ W,
                                              float* __restrict__ out) {
    __shared__ SmemU sm;

    prep_x_phase(sm, x);
    prep_w_phase(W);
    gridbar();

    // iter 1 (c = 0.1 baked into A0)
    sgemm_phase(sm);
    gridbar();
    squash_phase(out, 0);
    gridbar();
    uv_phase(sm, 1);
    gridbar();
    // iter 2
    sgemm_phase(sm);
    gridbar();
    squash_phase(out, 0);
    gridbar();
    uv_phase(sm, 0);
    gridbar();
    // iter 3
    sgemm_phase(sm);
    gridbar();
    squash_phase(out, 1);
}

// ---------------------------------------------------------------------------
extern "C" void kernel_launch(void* const* d_in, const int* in_sizes, int n_in,
                              void* d_out, int out_size) {
    const float* x = (const float*)d_in[0];   // (256, 8, 1152) fp32
    const float* W = (const float*)d_in[1];   // (1, 1152, 10, 16, 8) fp32
    float* out = (float*)d_out;               // (256, 10, 16, 1) fp32

    k_mega<<<NBLK, 256>>>(x, W, out);
}